// round 15
// baseline (speedup 1.0000x reference)
#include <cuda_runtime.h>
#include <cuda_fp16.h>
#include <cstdint>

#define N_NODES 50000
#define MAX_E   800000
#define DIM     128
#define DOUT    64

// Scratch (no allocations allowed -> __device__ globals)
__device__ int     g_deg[N_NODES];
__device__ int     g_rowptr[N_NODES + 1];
__device__ int     g_cursor[N_NODES];
__device__ unsigned long long g_blk_desc[256]; // lookback: (flag<<32)|value
__device__ float   g_dinv[N_NODES];
__device__ int     g_esrc[MAX_E];
__device__ __half2 g_xs[(size_t)N_NODES * (DIM / 2)]; // dinv[n] * x[n], fp16
__device__ __half2 g_hs[(size_t)N_NODES * (DIM / 2)]; // dinv[n] * relu(h[n]), fp16
__device__ float   g_agg0[(size_t)N_NODES * DIM];     // Adj @ xs
__device__ float   g_agg2[(size_t)N_NODES * DIM];     // Adj @ hs

// ---------------------------------------------------------------------------
// Histogram over dst
// ---------------------------------------------------------------------------
__global__ void hist_kernel(const int* __restrict__ dst, int E) {
    int e = blockIdx.x * blockDim.x + threadIdx.x;
    if (e < E) atomicAdd(&g_deg[dst[e]], 1);
}

// ---------------------------------------------------------------------------
// Single-pass exclusive scan of g_deg -> g_rowptr via decoupled lookback.
// Also computes g_dinv. Blocks only wait on lower-id predecessors (deadlock-
// free: 196 blocks fit in one wave; predecessors always scheduled first).
// flag: 1 = aggregate published, 2 = inclusive prefix published.
// ---------------------------------------------------------------------------
__global__ void scan_kernel(int N, int E) {
    __shared__ int tmp[256];
    __shared__ int s_prev;
    int t = threadIdx.x;
    int b = blockIdx.x;
    int i = b * 256 + t;
    int v = (i < N) ? g_deg[i] : 0;
    tmp[t] = v;
    __syncthreads();
#pragma unroll
    for (int off = 1; off < 256; off <<= 1) {
        int x = (t >= off) ? tmp[t - off] : 0;
        __syncthreads();
        tmp[t] += x;
        __syncthreads();
    }
    int blockSum = tmp[255];

    if (t == 0) {
        // Publish aggregate, then look back for exclusive prefix.
        atomicExch(&g_blk_desc[b], (1ULL << 32) | (unsigned)blockSum);
        long long running = 0;
        for (int p = b - 1; p >= 0; p--) {
            unsigned long long d;
            do {
                d = atomicAdd(&g_blk_desc[p], 0ULL);   // atomic read
            } while ((d >> 32) == 0ULL);
            running += (int)(d & 0xffffffffULL);
            if ((d >> 32) == 2ULL) break;              // hit a full prefix
        }
        atomicExch(&g_blk_desc[b],
                   (2ULL << 32) | (unsigned)(running + blockSum));
        s_prev = (int)running;
    }
    __syncthreads();
    int prev = s_prev;

    if (i < N) {
        g_rowptr[i] = prev + tmp[t] - v;               // exclusive scan
        int d = g_deg[i];
        g_dinv[i] = (d > 0) ? rsqrtf((float)d) : 0.0f;
    }
    if (b == 0 && t == 0) g_rowptr[N] = E;
}

// ---------------------------------------------------------------------------
// Fused: fill edge list grouped by dst (src index only) + prescale
// xs[n] = fp16(x[n] * dinv[n]).  Grid covers max(E, N*32) threads.
// ---------------------------------------------------------------------------
__global__ void fill_prescale_kernel(const int* __restrict__ src,
                                     const int* __restrict__ dst,
                                     const float* __restrict__ x,
                                     int E, int N) {
    int i = blockIdx.x * blockDim.x + threadIdx.x;

    if (i < N * 32) {          // prescale: 32 float4-lanes per node
        float s = g_dinv[i >> 5];
        float4 v = ((const float4*)x)[i];
        uint2 u;
        *(__half2*)&u.x = __floats2half2_rn(v.x * s, v.y * s);
        *(__half2*)&u.y = __floats2half2_rn(v.z * s, v.w * s);
        ((uint2*)g_xs)[i] = u;
    }
    if (i < E) {               // fill: one edge per thread
        int d = dst[i];
        int pos = g_rowptr[d] + atomicAdd(&g_cursor[d], 1);
        g_esrc[pos] = src[i];
    }
}

// ---------------------------------------------------------------------------
// Aggregation: out[n] = sum_{edges e with dst=n} feat[src_e]   (fp16 gather,
// fp32 accumulate). One warp per node; lane handles 4 halves (8B).
// (UNCHANGED from R13 — 4th kernel launch, so ncu profiles this.)
// ---------------------------------------------------------------------------
__global__ __launch_bounds__(256) void agg_kernel(
    const __half2* __restrict__ feat,
    float* __restrict__ out,
    int N)
{
    int node = blockIdx.x * 8 + (threadIdx.x >> 5);
    int lane = threadIdx.x & 31;
    if (node >= N) return;

    int beg = g_rowptr[node];
    int end = g_rowptr[node + 1];

    float4 acc = make_float4(0.f, 0.f, 0.f, 0.f);
    const uint2* f = (const uint2*)feat;  // row = 32 x uint2 (256B)

    int j = beg;
    for (; j + 4 <= end; j += 4) {
        int s0 = __ldg(g_esrc + j);
        int s1 = __ldg(g_esrc + j + 1);
        int s2 = __ldg(g_esrc + j + 2);
        int s3 = __ldg(g_esrc + j + 3);
        uint2 u0 = __ldg(&f[(size_t)s0 * 32 + lane]);
        uint2 u1 = __ldg(&f[(size_t)s1 * 32 + lane]);
        uint2 u2 = __ldg(&f[(size_t)s2 * 32 + lane]);
        uint2 u3 = __ldg(&f[(size_t)s3 * 32 + lane]);
#pragma unroll
        for (int q = 0; q < 4; q++) {
            uint2 u = (q == 0) ? u0 : (q == 1) ? u1 : (q == 2) ? u2 : u3;
            float2 fa = __half22float2(*(__half2*)&u.x);
            float2 fb = __half22float2(*(__half2*)&u.y);
            acc.x += fa.x; acc.y += fa.y; acc.z += fb.x; acc.w += fb.y;
        }
    }
    for (; j < end; j++) {
        int s0 = __ldg(g_esrc + j);
        uint2 u = __ldg(&f[(size_t)s0 * 32 + lane]);
        float2 fa = __half22float2(*(__half2*)&u.x);
        float2 fb = __half22float2(*(__half2*)&u.y);
        acc.x += fa.x; acc.y += fa.y; acc.z += fb.x; acc.w += fb.y;
    }
    ((float4*)out)[(size_t)node * 32 + lane] = acc;
}

// ---------------------------------------------------------------------------
// GEMM 1: hs = dinv ⊙ relu((dinv ⊙ agg0) @ W + b)  (fp16 output)
// Block: 256 thr = 8 warps; tile 64 rows x 128 cols; thread: 8 rows x 4 cols.
// ---------------------------------------------------------------------------
__global__ __launch_bounds__(256) void gemm_relu_kernel(
    const float* __restrict__ A,
    const float* __restrict__ W,
    const float* __restrict__ bias,
    __half2* __restrict__ outh,
    int M)
{
    __shared__ float sA[64][DIM];
    int warp = threadIdx.x >> 5;
    int lane = threadIdx.x & 31;
    int rowBase = blockIdx.x * 64;

    // Cooperative load of A tile, scaled by dinv[row]
    for (int i = threadIdx.x; i < 64 * 32; i += 256) {
        int r = i >> 5, c4 = i & 31;
        int gr = rowBase + r;
        float4 v = make_float4(0.f, 0.f, 0.f, 0.f);
        if (gr < M) {
            float s = g_dinv[gr];
            v = ((const float4*)(A + (size_t)gr * DIM))[c4];
            v.x *= s; v.y *= s; v.z *= s; v.w *= s;
        }
        ((float4*)sA[r])[c4] = v;
    }
    __syncthreads();

    int r0 = warp * 8;
    float4 acc[8];
#pragma unroll
    for (int r = 0; r < 8; r++) acc[r] = make_float4(0.f, 0.f, 0.f, 0.f);

#pragma unroll 4
    for (int k = 0; k < DIM; k += 2) {
        float4 w0 = ((const float4*)(W + (size_t)k * DIM))[lane];
        float4 w1 = ((const float4*)(W + (size_t)(k + 1) * DIM))[lane];
#pragma unroll
        for (int r = 0; r < 8; r++) {
            float2 a = *(const float2*)&sA[r0 + r][k];
            acc[r].x += a.x * w0.x; acc[r].y += a.x * w0.y;
            acc[r].z += a.x * w0.z; acc[r].w += a.x * w0.w;
            acc[r].x += a.y * w1.x; acc[r].y += a.y * w1.y;
            acc[r].z += a.y * w1.z; acc[r].w += a.y * w1.w;
        }
    }

    float4 b = ((const float4*)bias)[lane];
#pragma unroll
    for (int r = 0; r < 8; r++) {
        int row = rowBase + r0 + r;
        if (row < M) {
            float s = g_dinv[row];
            float rx = fmaxf(acc[r].x + b.x, 0.f) * s;
            float ry = fmaxf(acc[r].y + b.y, 0.f) * s;
            float rz = fmaxf(acc[r].z + b.z, 0.f) * s;
            float rw = fmaxf(acc[r].w + b.w, 0.f) * s;
            uint2 u;
            *(__half2*)&u.x = __floats2half2_rn(rx, ry);
            *(__half2*)&u.y = __floats2half2_rn(rz, rw);
            ((uint2*)outh)[(size_t)row * 32 + lane] = u;
        }
    }
}

// ---------------------------------------------------------------------------
// GEMM 2: mu = (dinv ⊙ A) @ Wmu + bmu (lanes 0..15),
//         ls = (dinv ⊙ A) @ Wls + bls (lanes 16..31)
// Outputs [M,64] each, concatenated: mu at [0, M*64), logstd after.
// ---------------------------------------------------------------------------
__global__ __launch_bounds__(256) void gemm_out_kernel(
    const float* __restrict__ A,
    const float* __restrict__ Wmu,
    const float* __restrict__ bmu,
    const float* __restrict__ Wls,
    const float* __restrict__ bls,
    float* __restrict__ out,
    int M)
{
    __shared__ float sA[64][DIM];
    int warp = threadIdx.x >> 5;
    int lane = threadIdx.x & 31;
    int rowBase = blockIdx.x * 64;

    for (int i = threadIdx.x; i < 64 * 32; i += 256) {
        int r = i >> 5, c4 = i & 31;
        int gr = rowBase + r;
        float4 v = make_float4(0.f, 0.f, 0.f, 0.f);
        if (gr < M) {
            float s = g_dinv[gr];
            v = ((const float4*)(A + (size_t)gr * DIM))[c4];
            v.x *= s; v.y *= s; v.z *= s; v.w *= s;
        }
        ((float4*)sA[r])[c4] = v;
    }
    __syncthreads();

    const float* Wsel = (lane < 16) ? Wmu : Wls;
    const float* bsel = (lane < 16) ? bmu : bls;
    float* obase = (lane < 16) ? out : out + (size_t)M * DOUT;
    int c = (lane & 15) * 4;

    int r0 = warp * 8;
    float4 acc[8];
#pragma unroll
    for (int r = 0; r < 8; r++) acc[r] = make_float4(0.f, 0.f, 0.f, 0.f);

#pragma unroll 4
    for (int k = 0; k < DIM; k += 2) {
        float4 w0 = *(const float4*)(Wsel + (size_t)k * DOUT + c);
        float4 w1 = *(const float4*)(Wsel + (size_t)(k + 1) * DOUT + c);
#pragma unroll
        for (int r = 0; r < 8; r++) {
            float2 a = *(const float2*)&sA[r0 + r][k];
            acc[r].x += a.x * w0.x; acc[r].y += a.x * w0.y;
            acc[r].z += a.x * w0.z; acc[r].w += a.x * w0.w;
            acc[r].x += a.y * w1.x; acc[r].y += a.y * w1.y;
            acc[r].z += a.y * w1.z; acc[r].w += a.y * w1.w;
        }
    }

    float4 b = *(const float4*)(bsel + c);
#pragma unroll
    for (int r = 0; r < 8; r++) {
        int row = rowBase + r0 + r;
        if (row < M) {
            float4 res;
            res.x = acc[r].x + b.x;
            res.y = acc[r].y + b.y;
            res.z = acc[r].z + b.z;
            res.w = acc[r].w + b.w;
            *(float4*)(obase + (size_t)row * DOUT + c) = res;
        }
    }
}

// ---------------------------------------------------------------------------
// Launch
// ---------------------------------------------------------------------------
extern "C" void kernel_launch(void* const* d_in, const int* in_sizes, int n_in,
                              void* d_out, int out_size) {
    const float* x    = (const float*)d_in[0];   // [N, 128]
    const int*   eidx = (const int*)d_in[1];     // [2, E] int32
    const float* w1   = (const float*)d_in[2];   // [128, 128]
    const float* b1   = (const float*)d_in[3];   // [128]
    const float* w_mu = (const float*)d_in[4];   // [128, 64]
    const float* b_mu = (const float*)d_in[5];   // [64]
    const float* w_ls = (const float*)d_in[6];   // [128, 64]
    const float* b_ls = (const float*)d_in[7];   // [64]
    float* out = (float*)d_out;

    int N = in_sizes[0] / DIM;       // 50000
    int E = in_sizes[1] / 2;         // 800000
    const int* src = eidx;
    const int* dst = eidx + E;

    // Zero histogram, cursors, lookback descriptors
    void *p_deg, *p_cur, *p_desc;
    cudaGetSymbolAddress(&p_deg, g_deg);
    cudaGetSymbolAddress(&p_cur, g_cursor);
    cudaGetSymbolAddress(&p_desc, g_blk_desc);
    cudaMemsetAsync(p_deg, 0, (size_t)N_NODES * sizeof(int));
    cudaMemsetAsync(p_cur, 0, (size_t)N_NODES * sizeof(int));
    cudaMemsetAsync(p_desc, 0, 256 * sizeof(unsigned long long));

    float *agg0, *agg2;
    __half2 *xs, *hs;
    cudaGetSymbolAddress((void**)&agg0, g_agg0);
    cudaGetSymbolAddress((void**)&agg2, g_agg2);
    cudaGetSymbolAddress((void**)&xs, g_xs);
    cudaGetSymbolAddress((void**)&hs, g_hs);

    int eblocks = (E + 255) / 256;
    int nblocks = (N + 255) / 256;   // 196
    int fpgrid  = (N * 32 > E ? N * 32 : E);
    int fpblocks = (fpgrid + 255) / 256;

    // CSR build: 3 kernels (hist, lookback scan + dinv, fill + prescale)
    hist_kernel<<<eblocks, 256>>>(dst, E);                       // launch 1
    scan_kernel<<<nblocks, 256>>>(N, E);                         // launch 2
    fill_prescale_kernel<<<fpblocks, 256>>>(src, dst, x, E, N);  // launch 3

    int ablocks = (N + 7) / 8;       // warp per node
    int gblocks = (N + 63) / 64;

    // Layer 1  (agg = 4th kernel launch -> gets the ncu profile)
    agg_kernel<<<ablocks, 256>>>(xs, agg0, N);                   // launch 4
    gemm_relu_kernel<<<gblocks, 256>>>(agg0, w1, b1, hs, N);     // launch 5

    // Layer 2
    agg_kernel<<<ablocks, 256>>>(hs, agg2, N);                   // launch 6
    gemm_out_kernel<<<gblocks, 256>>>(agg2, w_mu, b_mu, w_ls, b_ls, out, N); // 7
}